// round 10
// baseline (speedup 1.0000x reference)
#include <cuda_runtime.h>
#include <cstdint>

#define BB 64
#define SS 512
#define EE 256
#define HH 512
#define FH 2048
#define NBLK 128
#define NT 512

__device__ float g_hs[2][BB * HH];
__device__ float g_cs[2][BB * HH];
__device__ float g_u[(size_t)SS * BB * FH];  // [s][b][4H]
__device__ unsigned g_cnt;                   // monotonic barrier counter

// smem float offsets
#define SW_OFF 0                     // weights [40 rows][516]
#define SH_OFF (40 * 516)            // 20640: h state [32][516]
#define SC_OFF (SH_OFF + 32 * 516)   // 37152: c state [32][516]
#define SRED_OFF SH_OFF              // reduction aliases h-state region
#define SM_TOTF (SC_OFF + 32 * 516)  // 53664 floats = 214656 B

// ---------------------------------------------------------------------------
__device__ __forceinline__ void ffma2(unsigned long long& d,
                                      unsigned long long a,
                                      unsigned long long b) {
    asm volatile("fma.rn.f32x2 %0, %1, %2, %0;" : "+l"(d) : "l"(a), "l"(b));
}
__device__ __forceinline__ float lo32(unsigned long long v) {
    return __uint_as_float((unsigned)(v & 0xffffffffull));
}
__device__ __forceinline__ float hi32(unsigned long long v) {
    return __uint_as_float((unsigned)(v >> 32));
}
__device__ __forceinline__ float tanha(float x) {
    float y;
    asm("tanh.approx.f32 %0, %1;" : "=f"(y) : "f"(x));
    return y;
}
__device__ __forceinline__ float sigm(float x) {
    return 0.5f * tanha(0.5f * x) + 0.5f;
}
__device__ __forceinline__ uint32_t smem_u32(const void* p) {
    uint32_t a;
    asm("{ .reg .u64 t; cvta.to.shared.u64 t, %1; cvt.u32.u64 %0, t; }"
        : "=r"(a) : "l"(p));
    return a;
}
__device__ __forceinline__ void cpasync16(uint32_t dst, const void* src) {
    asm volatile("cp.async.cg.shared.global [%0], [%1], 16;"
                 :: "r"(dst), "l"(src));
}
#define CP_COMMIT() asm volatile("cp.async.commit_group;")
#define CP_WAIT0()  asm volatile("cp.async.wait_group 0;")

// Monotonic grid barrier: no resets, replay-safe.
__device__ __forceinline__ void gridbar() {
    __syncthreads();
    if (threadIdx.x == 0) {
        __threadfence();
        unsigned my = atomicAdd(&g_cnt, 1u);
        unsigned target = (my / NBLK + 1u) * NBLK;
        unsigned v;
        do {
            asm volatile("ld.acquire.gpu.global.u32 %0, [%1];"
                         : "=r"(v) : "l"(&g_cnt) : "memory");
        } while (v < target);
    }
    __syncthreads();
}

// ---------------------------------------------------------------------------
// ONE kernel: [phase 1] u_all GEMM (tiles round-robin) -> grid barrier ->
// [phase 2] 512-step recurrence with smem-resident weights -> tail.
// Block = (jt = bid>>1 -> 8 j-columns, bh = bid&1 -> 32 batches).
// Recurrence thread: ks = t>>6 (k-slice of 64), jg = (t>>4)&3, bp = t&15;
// per thread 2 j (jg*2+ji) x 2 batches (bp+16*bi), k-packed f32x2 accs.
// ---------------------------------------------------------------------------
__global__ __launch_bounds__(NT, 1) void lstm_fused(
    const float* __restrict__ X,
    const float* __restrict__ ts,
    const float* __restrict__ Wall,
    const float* __restrict__ Wall_b,
    const float* __restrict__ U,
    const float* __restrict__ Ub,
    const float* __restrict__ Wd,
    const float* __restrict__ Wd_b,
    float* __restrict__ out,
    int write_tail)
{
    extern __shared__ float sm[];
    const uint32_t smb = smem_u32(sm);
    const int t = threadIdx.x;
    const int jt = blockIdx.x >> 1;
    const int bh = blockIdx.x & 1;
    const int j0 = jt * 8;

    // --- one-time weight slice: rows [g*8+jl][516], 20480 elems, 40/thread
#pragma unroll 4
    for (int it = 0; it < 40; it++) {
        int i = t + NT * it;
        int g = i >> 12, jl = (i >> 9) & 7, k = i & 511;
        sm[SW_OFF + (g * 8 + jl) * 516 + k] =
            (g < 4) ? Wall[(size_t)(g * HH + j0 + jl) * HH + k]
                    : Wd[(size_t)(j0 + jl) * HH + k];
    }

    // ===================== Phase 1: u_all GEMM =====================
    // tile = s*16 + nt: 64 batches x 128 cols at seq position s.
    {
        float2* sA = (float2*)(sm + SH_OFF);   // [32 mpair][32 k]
        float2* sB = sA + 1024;                // [128 n][34]
        const int tx = t & 15;
        const int ty = t >> 4;                 // 0..31 mpair
        for (int tile = blockIdx.x; tile < 8192; tile += NBLK) {
            int s = tile >> 4, n0 = (tile & 15) * 128;
            unsigned long long acc[8];
#pragma unroll
            for (int i = 0; i < 8; i++) acc[i] = 0ull;
            for (int k0 = 0; k0 < EE; k0 += 32) {
#pragma unroll
                for (int r = 0; r < 2; r++) {
                    int i = t + NT * r;
                    int p = i >> 5, k = i & 31;
                    sA[p * 32 + k] = make_float2(
                        X[((size_t)(2 * p) * SS + s) * EE + k0 + k],
                        X[((size_t)(2 * p + 1) * SS + s) * EE + k0 + k]);
                }
#pragma unroll
                for (int r = 0; r < 8; r++) {
                    int i = t + NT * r;
                    int n = i >> 5, k = i & 31;
                    float w = U[(size_t)(n0 + n) * EE + k0 + k];
                    sB[n * 34 + k] = make_float2(w, w);
                }
                __syncthreads();
#pragma unroll
                for (int k = 0; k < 32; k += 2) {
                    unsigned long long a0 = *(unsigned long long*)&sA[ty * 32 + k];
                    unsigned long long a1 = *(unsigned long long*)&sA[ty * 32 + k + 1];
#pragma unroll
                    for (int n8 = 0; n8 < 8; n8++) {
                        const unsigned long long* bp_ =
                            (const unsigned long long*)&sB[(tx + 16 * n8) * 34 + k];
                        ffma2(acc[n8], a0, bp_[0]);
                        ffma2(acc[n8], a1, bp_[1]);
                    }
                }
                __syncthreads();
            }
#pragma unroll
            for (int n8 = 0; n8 < 8; n8++) {
                int n = n0 + tx + 16 * n8;
                float bv = Ub[n];
                g_u[((size_t)s * BB + 2 * ty) * FH + n]     = lo32(acc[n8]) + bv;
                g_u[((size_t)s * BB + 2 * ty + 1) * FH + n] = hi32(acc[n8]) + bv;
            }
        }
    }
    gridbar();

    // ===================== Phase 2: recurrence =====================
    const int ks = t >> 6;
    const int jg = (t >> 4) & 3;
    const int bp = t & 15;
    // epilogue identity (t < 256): output cell = jl*32 + bl
    const int ejl = t >> 5;
    const int ebl = t & 31;
    const int ej  = j0 + ejl;
    const int ebg = bh * 32 + ebl;
    float zbf = 0, zbi = 0, zbo = 0, zbg = 0, zbd = 0;
    if (t < 256) {
        zbf = Wall_b[ej];
        zbi = Wall_b[HH + ej];
        zbo = Wall_b[2 * HH + ej];
        zbg = Wall_b[3 * HH + ej];
        zbd = Wd_b[ej];
    }

    for (int s = 0; s < SS; s++) {
        const int par = s & 1;
        const float* hp = g_hs[par];
        const float* cpp = g_cs[par];
        float* hn = g_hs[par ^ 1];
        float* cn = g_cs[par ^ 1];

        float uf = 0, ui = 0, uo = 0, ug = 0, cold = 0, tsv = 0;
        if (t < 256) {
            const float* ub = g_u + ((size_t)s * BB + ebg) * FH;
            uf = __ldcs(ub + ej);
            ui = __ldcs(ub + HH + ej);
            uo = __ldcs(ub + 2 * HH + ej);
            ug = __ldcs(ub + 3 * HH + ej);
            if (s) cold = __ldcg(cpp + (size_t)ebg * HH + ej);
            tsv = __ldg(ts + (size_t)ebg * SS + s);
        }

        if (s == 0) {
            float4 z = make_float4(0.f, 0.f, 0.f, 0.f);
#pragma unroll
            for (int q = 0; q < 9; q++) {
                int i = t + NT * q;
                if (i < 4128) {
                    ((float4*)(sm + SH_OFF))[i] = z;
                    ((float4*)(sm + SC_OFF))[i] = z;
                }
            }
            __syncthreads();
        } else {
#pragma unroll
            for (int q = 0; q < 8; q++) {
                int i = t + NT * q;
                int b = i >> 7, k4 = i & 127;
                cpasync16(smb + (uint32_t)((SH_OFF + b * 516 + k4 * 4) * 4),
                          hp + (size_t)(bh * 32 + b) * HH + k4 * 4);
                cpasync16(smb + (uint32_t)((SC_OFF + b * 516 + k4 * 4) * 4),
                          cpp + (size_t)(bh * 32 + b) * HH + k4 * 4);
            }
            CP_COMMIT();
            CP_WAIT0();
            __syncthreads();
        }

        unsigned long long acc[5][2][2];
#pragma unroll
        for (int g = 0; g < 5; g++)
#pragma unroll
            for (int ji = 0; ji < 2; ji++) {
                acc[g][ji][0] = 0ull;
                acc[g][ji][1] = 0ull;
            }

        const float* hA = sm + SH_OFF + bp * 516 + ks * 64;
        const float* hB = hA + 16 * 516;
        const float* cA = sm + SC_OFF + bp * 516 + ks * 64;
        const float* cB = cA + 16 * 516;
        const float* wb = sm + SW_OFF + (jg * 2) * 516 + ks * 64;

#pragma unroll 4
        for (int m = 0; m < 16; m++) {
            ulonglong2 h0 = *(const ulonglong2*)(hA + m * 4);
            ulonglong2 h1 = *(const ulonglong2*)(hB + m * 4);
            ulonglong2 c0 = *(const ulonglong2*)(cA + m * 4);
            ulonglong2 c1 = *(const ulonglong2*)(cB + m * 4);
#pragma unroll
            for (int g = 0; g < 5; g++)
#pragma unroll
                for (int ji = 0; ji < 2; ji++) {
                    ulonglong2 w = *(const ulonglong2*)(wb + (g * 8 + ji) * 516 + m * 4);
                    if (g < 4) {
                        ffma2(acc[g][ji][0], h0.x, w.x);
                        ffma2(acc[g][ji][0], h0.y, w.y);
                        ffma2(acc[g][ji][1], h1.x, w.x);
                        ffma2(acc[g][ji][1], h1.y, w.y);
                    } else {
                        ffma2(acc[g][ji][0], c0.x, w.x);
                        ffma2(acc[g][ji][0], c0.y, w.y);
                        ffma2(acc[g][ji][1], c1.x, w.x);
                        ffma2(acc[g][ji][1], c1.y, w.y);
                    }
                }
        }
        __syncthreads();

        // scatter partials: R[ks][g][cell], cell = (jg*2+ji)*32 + bp + 16*bi
        {
            float* R = sm + SRED_OFF + ks * 1280;
#pragma unroll
            for (int g = 0; g < 5; g++)
#pragma unroll
                for (int ji = 0; ji < 2; ji++)
#pragma unroll
                    for (int bi = 0; bi < 2; bi++) {
                        int cellv = (jg * 2 + ji) * 32 + bp + 16 * bi;
                        R[g * 256 + cellv] =
                            lo32(acc[g][ji][bi]) + hi32(acc[g][ji][bi]);
                    }
        }
        __syncthreads();

        if (t < 256) {
            float s0 = 0, s1 = 0, s2 = 0, s3 = 0, s4 = 0;
#pragma unroll
            for (int k2 = 0; k2 < 8; k2++) {
                const float* R = sm + SRED_OFF + k2 * 1280 + t;
                s0 += R[0];
                s1 += R[256];
                s2 += R[512];
                s3 += R[768];
                s4 += R[1024];
            }
            float pf = s0 + zbf + uf;
            float pi = s1 + zbi + ui;
            float po = s2 + zbo + uo;
            float pg = s3 + zbg + ug;
            float dd = s4 + zbd;

            float cs1 = tanha(dd);
            float cadj = (cold - cs1) + cs1 * tsv;
            float fg = sigm(pf);
            float ig = sigm(pi);
            float og = sigm(po);
            float cg = sigm(pg);
            float cnew = fg * cadj + ig * cg;
            float hnew = og * tanha(cnew);

            __stcg(hn + (size_t)ebg * HH + ej, hnew);
            __stcg(cn + (size_t)ebg * HH + ej, cnew);
            out[((size_t)ebg * SS + s) * HH + ej] = hnew;
            if (s == SS - 1 && write_tail) {
                out[(size_t)BB * SS * HH + (size_t)ebg * HH + ej] = hnew;
                out[(size_t)BB * SS * HH + (size_t)BB * HH +
                    (size_t)ebg * HH + ej] = cnew;
            }
        }

        if (s != SS - 1) gridbar();
    }
}

// ---------------------------------------------------------------------------
extern "C" void kernel_launch(void* const* d_in, const int* in_sizes, int n_in,
                              void* d_out, int out_size) {
    const float* X      = (const float*)d_in[0];
    const float* ts     = (const float*)d_in[1];
    const float* Wall   = (const float*)d_in[2];
    const float* Wall_b = (const float*)d_in[3];
    const float* U      = (const float*)d_in[4];
    const float* Ub     = (const float*)d_in[5];
    const float* Wd     = (const float*)d_in[6];
    const float* Wdb    = (const float*)d_in[7];
    float* out = (float*)d_out;

    cudaFuncSetAttribute(lstm_fused,
                         cudaFuncAttributeMaxDynamicSharedMemorySize,
                         SM_TOTF * (int)sizeof(float));

    long long need = (long long)BB * SS * HH + 2LL * BB * HH;
    int write_tail = ((long long)out_size >= need) ? 1 : 0;

    lstm_fused<<<NBLK, NT, SM_TOTF * sizeof(float)>>>(
        X, ts, Wall, Wall_b, U, Ub, Wd, Wdb, out, write_tail);
}

// round 12
// speedup vs baseline: 1.6953x; 1.6953x over previous
#include <cuda_runtime.h>
#include <cuda_bf16.h>
#include <cstdint>

#define BB 64
#define SS 512
#define EE 256
#define HH 512
#define FH 2048
#define NBLK 128
#define NT 256

// smem byte offsets (dynamic)
#define WH 0                 // weight hi: 40 rows x 520 bf16 (pitch 1040B)
#define WL 41600
#define PH 83200             // state planes: 32 rows x 520 bf16 each
#define PHL 116480
#define PC 149760
#define PCL 183040
#define BIASB 216320         // 40 floats
#define RED 83200            // reduce scratch aliases PH (20480B)
#define SMEM_DYN 216480
#define PITCH 1040

__device__ __align__(16) __nv_bfloat16 g_hhi[BB * HH];
__device__ __align__(16) __nv_bfloat16 g_hlo[BB * HH];
__device__ __align__(16) __nv_bfloat16 g_chi[BB * HH];
__device__ __align__(16) __nv_bfloat16 g_clo[BB * HH];
__device__ float g_u[(size_t)SS * BB * FH];
__device__ unsigned g_cnt;

// ---------------------------------------------------------------------------
__device__ __forceinline__ uint32_t smem_u32(const void* p) {
    uint32_t a;
    asm("{ .reg .u64 t; cvta.to.shared.u64 t, %1; cvt.u32.u64 %0, t; }"
        : "=r"(a) : "l"(p));
    return a;
}
__device__ __forceinline__ void cpasync16(uint32_t dst, const void* src) {
    asm volatile("cp.async.cg.shared.global [%0], [%1], 16;"
                 :: "r"(dst), "l"(src));
}
#define CP_COMMIT() asm volatile("cp.async.commit_group;")
#define CP_WAIT0()  asm volatile("cp.async.wait_group 0;")
__device__ __forceinline__ unsigned short f2bf(float x) {
    unsigned short r;
    asm("cvt.rn.bf16.f32 %0, %1;" : "=h"(r) : "f"(x));
    return r;
}
__device__ __forceinline__ float bf2f(unsigned short u) {
    return __uint_as_float(((unsigned)u) << 16);
}
__device__ __forceinline__ float tanha(float x) {
    float y;
    asm("tanh.approx.f32 %0, %1;" : "=f"(y) : "f"(x));
    return y;
}
__device__ __forceinline__ float sigm(float x) {
    return 0.5f * tanha(0.5f * x) + 0.5f;
}
#define LDM4(r, a) \
    asm volatile("ldmatrix.sync.aligned.m8n8.x4.shared.b16 {%0,%1,%2,%3},[%4];" \
        : "=r"((r)[0]), "=r"((r)[1]), "=r"((r)[2]), "=r"((r)[3]) : "r"(a))
#define LDM2(r0, r1, a) \
    asm volatile("ldmatrix.sync.aligned.m8n8.x2.shared.b16 {%0,%1},[%2];" \
        : "=r"(r0), "=r"(r1) : "r"(a))
#define MMA(d, a, b0, b1) \
    asm volatile("mma.sync.aligned.m16n8k16.row.col.f32.bf16.bf16.f32 " \
        "{%0,%1,%2,%3},{%4,%5,%6,%7},{%8,%9},{%0,%1,%2,%3};" \
        : "+f"((d)[0]), "+f"((d)[1]), "+f"((d)[2]), "+f"((d)[3]) \
        : "r"((a)[0]), "r"((a)[1]), "r"((a)[2]), "r"((a)[3]), "r"(b0), "r"(b1))

__device__ __forceinline__ void gridbar() {
    __syncthreads();
    if (threadIdx.x == 0) {
        __threadfence();
        unsigned my = atomicAdd(&g_cnt, 1u);
        unsigned target = (my / NBLK + 1u) * NBLK;
        unsigned v;
        do {
            asm volatile("ld.acquire.gpu.global.u32 %0, [%1];"
                         : "=r"(v) : "l"(&g_cnt) : "memory");
        } while (v < target);
    }
    __syncthreads();
}

// ---------------------------------------------------------------------------
__global__ void init_kernel() {
    int i = blockIdx.x * blockDim.x + threadIdx.x;
    if (i < BB * HH / 2) {
        ((unsigned*)g_hhi)[i] = 0u;
        ((unsigned*)g_hlo)[i] = 0u;
        ((unsigned*)g_chi)[i] = 0u;
        ((unsigned*)g_clo)[i] = 0u;
    }
    if (i == 0) g_cnt = 0;
}

// ---------------------------------------------------------------------------
// u_all GEMM (FFMA2, as R7). g_u[s][b][4H].
// ---------------------------------------------------------------------------
__device__ __forceinline__ void ffma2(unsigned long long& d,
                                      unsigned long long a,
                                      unsigned long long b) {
    asm volatile("fma.rn.f32x2 %0, %1, %2, %0;" : "+l"(d) : "l"(a), "l"(b));
}
__global__ __launch_bounds__(256) void u_gemm_kernel(
    const float* __restrict__ X, const float* __restrict__ W,
    const float* __restrict__ Bv)
{
    __shared__ float2 sA[16][32];
    __shared__ float2 sB[128][34];
    int t = threadIdx.x, tx = t & 15, ty = t >> 4;
    int s = blockIdx.x >> 1, bh = blockIdx.x & 1, b0 = bh * 32;
    int n0 = blockIdx.y * 128;
    unsigned long long acc[8];
#pragma unroll
    for (int i = 0; i < 8; i++) acc[i] = 0ull;
    for (int k0 = 0; k0 < EE; k0 += 32) {
#pragma unroll
        for (int r = 0; r < 2; r++) {
            int i = t + 256 * r, p = i >> 5, k = i & 31, b = b0 + 2 * p;
            sA[p][k] = make_float2(X[((size_t)b * SS + s) * EE + k0 + k],
                                   X[((size_t)(b + 1) * SS + s) * EE + k0 + k]);
        }
#pragma unroll
        for (int r = 0; r < 16; r++) {
            int i = t + 256 * r, n = i >> 5, k = i & 31;
            float w = W[(size_t)(n0 + n) * EE + k0 + k];
            sB[n][k] = make_float2(w, w);
        }
        __syncthreads();
#pragma unroll
        for (int k = 0; k < 32; k += 2) {
            unsigned long long a0 = *(unsigned long long*)&sA[ty][k];
            unsigned long long a1 = *(unsigned long long*)&sA[ty][k + 1];
#pragma unroll
            for (int n8 = 0; n8 < 8; n8++) {
                const unsigned long long* bp =
                    (const unsigned long long*)&sB[tx + 16 * n8][k];
                ffma2(acc[n8], a0, bp[0]);
                ffma2(acc[n8], a1, bp[1]);
            }
        }
        __syncthreads();
    }
    int p = b0 / 2 + ty;
#pragma unroll
    for (int n8 = 0; n8 < 8; n8++) {
        int n = n0 + tx + 16 * n8;
        float bv = Bv[n];
        g_u[((size_t)s * BB + 2 * p) * FH + n] =
            __uint_as_float((unsigned)(acc[n8] & 0xffffffffull)) + bv;
        g_u[((size_t)s * BB + 2 * p + 1) * FH + n] =
            __uint_as_float((unsigned)(acc[n8] >> 32)) + bv;
    }
}

// ---------------------------------------------------------------------------
// Persistent mma.sync recurrence. 128 blocks = 64 j-tiles x 2 batch-halves.
// 8 warps = 2 m-tiles(16 batches) x 4 k-quarters(128). 3-pass split bf16.
// ---------------------------------------------------------------------------
__global__ __launch_bounds__(NT, 1) void lstm_mma(
    const float* __restrict__ Wall, const float* __restrict__ Wall_b,
    const float* __restrict__ Wd, const float* __restrict__ Wd_b,
    const float* __restrict__ ts, float* __restrict__ out, int write_tail)
{
    extern __shared__ char smc[];
    const uint32_t base = smem_u32(smc);
    const int t = threadIdx.x, wid = t >> 5, lane = t & 31;
    const int jt = blockIdx.x >> 1, bh = blockIdx.x & 1;
    const int j0 = jt * 8;
    const int mw = wid & 1, kq = wid >> 1;

    // ---- one-time: split weights into smem (40 rows x 512, pitch 1040B)
#pragma unroll 4
    for (int it = 0; it < 80; it++) {
        int i = t + NT * it;
        int r = i >> 9, k = i & 511;
        float w = (r < 32) ? Wall[(size_t)((r >> 3) * HH + j0 + (r & 7)) * HH + k]
                           : Wd[(size_t)(j0 + (r & 7)) * HH + k];
        unsigned short hi = f2bf(w);
        unsigned short lo = f2bf(w - bf2f(hi));
        *(unsigned short*)(smc + WH + r * PITCH + k * 2) = hi;
        *(unsigned short*)(smc + WL + r * PITCH + k * 2) = lo;
    }
    if (t < 40) {
        ((float*)(smc + BIASB))[t] =
            (t < 32) ? Wall_b[(t >> 3) * HH + j0 + (t & 7)]
                     : Wd_b[j0 + (t & 7)];
    }
    __syncthreads();

    // ---- persistent B-hi fragments: 5 slots x 8 k-tiles x 2 regs
    uint32_t bhi[5][8][2];
    {
        int l = lane & 15;
        int brow = l & 7, bk = (l >> 3) & 1;
#pragma unroll
        for (int ns = 0; ns < 5; ns++)
#pragma unroll
            for (int kt = 0; kt < 8; kt++) {
                uint32_t a = base + WH + (ns * 8 + brow) * PITCH +
                             (kq * 128 + kt * 16) * 2 + bk * 16;
                LDM2(bhi[ns][kt][0], bhi[ns][kt][1], a);
            }
    }
    // B-lo address base (per lane)
    const uint32_t bloAddr0 = base + WL + ((lane & 15) & 7) * PITCH +
                              (((lane & 15) >> 3) & 1) * 16 + kq * 256;
    // A ldmatrix per-lane base offset
    const uint32_t aoff = (mw * 16 + (lane & 15)) * PITCH + (lane >> 4) * 16 +
                          kq * 256;

    // epilogue identity
    const int eb = t >> 3, ejl = t & 7;
    const int bg = bh * 32 + eb, ej = j0 + ejl;
    const float zb0 = ((float*)(smc + BIASB))[ejl];
    const float zb1 = ((float*)(smc + BIASB))[8 + ejl];
    const float zb2 = ((float*)(smc + BIASB))[16 + ejl];
    const float zb3 = ((float*)(smc + BIASB))[24 + ejl];
    const float zb4 = ((float*)(smc + BIASB))[32 + ejl];
    float ccar = 0.f;

    for (int s = 0; s < SS; s++) {
        // epilogue operand prefetch
        const float* ur = g_u + ((size_t)s * BB + bg) * FH + ej;
        float u0 = __ldcs(ur);
        float u1 = __ldcs(ur + HH);
        float u2 = __ldcs(ur + 2 * HH);
        float u3 = __ldcs(ur + 3 * HH);
        float tsv = __ldg(ts + (size_t)bg * SS + s);

        // stage 4 state planes (32 rows x 512 bf16 each)
#pragma unroll
        for (int q = 0; q < 32; q++) {
            int i = t + NT * (q & 7);
            int row = i >> 6, seg = i & 63;
            int p = q >> 3;
            const __nv_bfloat16* gp =
                (p == 0) ? g_hhi : (p == 1) ? g_hlo : (p == 2) ? g_chi : g_clo;
            cpasync16(base + PH + p * 33280 + row * PITCH + seg * 16,
                      gp + (size_t)(bh * 32 + row) * HH + seg * 8);
        }
        CP_COMMIT();
        CP_WAIT0();
        __syncthreads();

        float acc[5][4];
#pragma unroll
        for (int ns = 0; ns < 5; ns++)
#pragma unroll
            for (int r = 0; r < 4; r++) acc[ns][r] = 0.f;

#pragma unroll
        for (int kt = 0; kt < 8; kt++) {
            uint32_t kb = kt * 32;
            uint32_t ahh[4], ahl[4], ach[4], acl[4];
            LDM4(ahh, base + PH + aoff + kb);
            LDM4(ahl, base + PHL + aoff + kb);
            LDM4(ach, base + PC + aoff + kb);
            LDM4(acl, base + PCL + aoff + kb);
            uint32_t bl[5][2];
#pragma unroll
            for (int ns = 0; ns < 5; ns++)
                LDM2(bl[ns][0], bl[ns][1], bloAddr0 + ns * 8 * PITCH + kb);
#pragma unroll
            for (int ns = 0; ns < 4; ns++) {
                MMA(acc[ns], ahh, bhi[ns][kt][0], bhi[ns][kt][1]);
                MMA(acc[ns], ahh, bl[ns][0], bl[ns][1]);
                MMA(acc[ns], ahl, bhi[ns][kt][0], bhi[ns][kt][1]);
            }
            MMA(acc[4], ach, bhi[4][kt][0], bhi[4][kt][1]);
            MMA(acc[4], ach, bl[4][0], bl[4][1]);
            MMA(acc[4], acl, bhi[4][kt][0], bhi[4][kt][1]);
        }
        __syncthreads();  // reduce scratch aliases PH plane

        // scatter partials: R[((kq*5+g)*32 + row)*8 + jl]
        {
            float* R = (float*)(smc + RED);
#pragma unroll
            for (int ns = 0; ns < 5; ns++)
#pragma unroll
                for (int r = 0; r < 4; r++) {
                    int row = mw * 16 + (lane >> 2) + (r >> 1) * 8;
                    int jl = (lane & 3) * 2 + (r & 1);
                    R[((kq * 5 + ns) * 32 + row) * 8 + jl] = acc[ns][r];
                }
        }
        __syncthreads();

        // gather + gate epilogue (each thread: one (batch, j))
        {
            const float* R = (float*)(smc + RED);
            float s0 = 0, s1 = 0, s2 = 0, s3 = 0, s4 = 0;
#pragma unroll
            for (int k2 = 0; k2 < 4; k2++) {
                const float* Rq = R + (k2 * 5 * 32 + eb) * 8 + ejl;
                s0 += Rq[0];
                s1 += Rq[32 * 8];
                s2 += Rq[64 * 8];
                s3 += Rq[96 * 8];
                s4 += Rq[128 * 8];
            }
            float pf = s0 + zb0 + u0;
            float pi = s1 + zb1 + u1;
            float po = s2 + zb2 + u2;
            float pg = s3 + zb3 + u3;
            float dd = s4 + zb4;

            float cs1 = tanha(dd);
            float cadj = (ccar - cs1) + cs1 * tsv;
            float cnew = sigm(pf) * cadj + sigm(pi) * sigm(pg);
            float hnew = sigm(po) * tanha(cnew);
            ccar = cnew;

            out[((size_t)bg * SS + s) * HH + ej] = hnew;

            unsigned short hh = f2bf(hnew);
            unsigned short hl = f2bf(hnew - bf2f(hh));
            unsigned short ch = f2bf(cnew);
            unsigned short cl = f2bf(cnew - bf2f(ch));
            size_t po_ = (size_t)bg * HH + ej;
            g_hhi[po_] = *(__nv_bfloat16*)&hh;
            g_hlo[po_] = *(__nv_bfloat16*)&hl;
            g_chi[po_] = *(__nv_bfloat16*)&ch;
            g_clo[po_] = *(__nv_bfloat16*)&cl;

            if (s == SS - 1 && write_tail) {
                out[(size_t)BB * SS * HH + po_] = hnew;
                out[(size_t)BB * SS * HH + (size_t)BB * HH + po_] = cnew;
            }
        }

        if (s != SS - 1) gridbar();
    }
}

// ---------------------------------------------------------------------------
extern "C" void kernel_launch(void* const* d_in, const int* in_sizes, int n_in,
                              void* d_out, int out_size) {
    const float* X      = (const float*)d_in[0];
    const float* ts     = (const float*)d_in[1];
    const float* Wall   = (const float*)d_in[2];
    const float* Wall_b = (const float*)d_in[3];
    const float* U      = (const float*)d_in[4];
    const float* Ub     = (const float*)d_in[5];
    const float* Wd     = (const float*)d_in[6];
    const float* Wdb    = (const float*)d_in[7];
    float* out = (float*)d_out;

    cudaFuncSetAttribute(lstm_mma, cudaFuncAttributeMaxDynamicSharedMemorySize,
                         SMEM_DYN);

    init_kernel<<<64, 256>>>();
    dim3 gu(SS * 2, FH / 128);
    u_gemm_kernel<<<gu, 256>>>(X, U, Ub);

    long long need = (long long)BB * SS * HH + 2LL * BB * HH;
    int write_tail = ((long long)out_size >= need) ? 1 : 0;
    lstm_mma<<<NBLK, NT, SMEM_DYN>>>(Wall, Wall_b, Wd, Wdb, ts, out, write_tail);
}